// round 15
// baseline (speedup 1.0000x reference)
#include <cuda_runtime.h>
#include <cuda_fp16.h>
#include <cstdint>

#define N        100000
#define FIN      512
#define HID      512
#define C        40
#define EDG      1600000
#define KITER    10
#define ALPHA    0.1f

// ---------------- scratch (device globals; no allocation allowed) ----------
__device__ float  g_Z0[(size_t)N * C];
__device__ float  g_ZA[(size_t)N * C];
__device__ float  g_ZB[(size_t)N * C];
__device__ __half g_HA[(size_t)N * C];   // fp16 shadow of z (gather-only)
__device__ __half g_HB[(size_t)N * C];
__device__ float  g_dinv[N];
__device__ int    g_deg[N];
__device__ int    g_base[N];
__device__ int    g_cursor[N];
__device__ int2   g_meta[EDG];
__device__ int    g_total;
__device__ float  g_w1t[(size_t)HID * FIN];  // W1^T [n][k], tf32-rounded

// ---------------- PTX helpers ----------------------------------------------
__device__ __forceinline__ uint32_t smem_u32(const void* p) {
    uint32_t a;
    asm("{ .reg .u64 t; cvta.to.shared.u64 t, %1; cvt.u32.u64 %0, t; }"
        : "=r"(a) : "l"(p));
    return a;
}
__device__ __forceinline__ void cp16(uint32_t s, const void* g) {
    asm volatile("cp.async.cg.shared.global [%0], [%1], 16;" :: "r"(s), "l"(g));
}
__device__ __forceinline__ void cp16p(uint32_t s, const void* g, int bytes) {
    asm volatile("cp.async.cg.shared.global [%0], [%1], 16, %2;"
                 :: "r"(s), "l"(g), "r"(bytes));
}
#define CP_COMMIT()  asm volatile("cp.async.commit_group;" ::: "memory")
#define CP_WAIT(n)   asm volatile("cp.async.wait_group %0;" :: "n"(n) : "memory")

__device__ __forceinline__ uint32_t to_tf32(float f) {
    uint32_t u;
    asm("cvt.rna.tf32.f32 %0, %1;" : "=r"(u) : "f"(f));
    return u;
}

#define LDSM4(r, a) \
    asm volatile("ldmatrix.sync.aligned.m8n8.x4.shared.b16 {%0,%1,%2,%3}, [%4];" \
        : "=r"((r)[0]), "=r"((r)[1]), "=r"((r)[2]), "=r"((r)[3]) : "r"(a))

#define MMA_TF32(d, a, b0, b1) \
    asm volatile("mma.sync.aligned.m16n8k8.row.col.f32.tf32.tf32.f32 " \
        "{%0,%1,%2,%3}, {%4,%5,%6,%7}, {%8,%9}, {%0,%1,%2,%3};" \
        : "+f"((d)[0]), "+f"((d)[1]), "+f"((d)[2]), "+f"((d)[3]) \
        : "r"((a)[0]), "r"((a)[1]), "r"((a)[2]), "r"((a)[3]), "r"(b0), "r"(b1))

// ---------------- setup -----------------------------------------------------
__global__ void k_deg_count(const int* __restrict__ ei) {
    int e = blockIdx.x * blockDim.x + threadIdx.x;
    if (e < EDG) atomicAdd(&g_deg[ei[e]], 1);
}
__global__ void k_dinv_base() {
    int i = blockIdx.x * blockDim.x + threadIdx.x;
    if (i < N) {
        int d = g_deg[i];
        g_dinv[i] = rsqrtf((float)d);
        int b = atomicAdd(&g_total, d - 1);
        g_base[i] = b;
        g_cursor[i] = b;
    }
}
__global__ void k_scatter(const int* __restrict__ ei) {
    int e = blockIdx.x * blockDim.x + threadIdx.x;
    if (e < EDG) {
        int r = ei[e];
        int s = ei[EDG + e];
        float w = (1.0f - ALPHA) * g_dinv[r] * g_dinv[s];
        int pos = atomicAdd(&g_cursor[r], 1);
        g_meta[pos] = make_int2(s, __float_as_int(w));
    }
}

// W1 [k][n] -> g_w1t [n][k], tf32-rounded
__global__ void k_cvt_w1(const float* __restrict__ W1) {
    __shared__ float t[32][33];
    int bx = blockIdx.x & 15, by = blockIdx.x >> 4;
    int tx = threadIdx.x & 31, ty = threadIdx.x >> 5;
    t[ty][tx] = W1[(size_t)(by * 32 + ty) * HID + bx * 32 + tx];
    __syncthreads();
    int n = bx * 32 + ty, k = by * 32 + tx;
    g_w1t[(size_t)n * FIN + k] = __uint_as_float(to_tf32(t[tx][ty]));
}

// z0 = b2 broadcast; folds deg/total reset
__global__ void k_z0init(const float* __restrict__ b2) {
    unsigned t = blockIdx.x * blockDim.x + threadIdx.x;
    if (t >= (unsigned)N * 10u) return;
    unsigned c = t % 10u;
    ((float4*)g_Z0)[t] = ((const float4*)b2)[c];
    if (t < N) g_deg[t] = 1;
    if (t == 0) g_total = 0;
}

// fp16 shadow seed: HA = half(Z0)
__global__ void k_h0() {
    unsigned t = blockIdx.x * blockDim.x + threadIdx.x;
    if (t >= (unsigned)N * 10u) return;
    float4 v = ((const float4*)g_Z0)[t];
    __half2 h01 = __floats2half2_rn(v.x, v.y);
    __half2 h23 = __floats2half2_rn(v.z, v.w);
    uint2 pk;
    pk.x = *(uint32_t*)&h01;
    pk.y = *(uint32_t*)&h23;
    ((uint2*)g_HA)[t] = pk;
}

// ---------------- TF32 GEMM1 + tensor-core GEMM2 epilogue (FROZEN) ----------
#define BK      32
#define SA      36
#define AROWS   96
#define BROWS   128
#define OFF_B   (AROWS * SA * 4)
#define STGB    ((AROWS + BROWS) * SA * 4)
#define NSTG    3
#define GEMM_SMEM (NSTG * STGB)           // 96768
#define TPB     192
#define MT      ((N + AROWS - 1) / AROWS) // 1042
#define HSS     132
#define EPI_W2  (AROWS * HSS * 4)
#define EPI_B1  (EPI_W2 + BROWS * C * 4)

__device__ __forceinline__ void prefetch(uint32_t sb, int stage,
                                         const float* __restrict__ x,
                                         int m0, int n0, int kc, int tid) {
    uint32_t st = sb + stage * STGB;
    #pragma unroll
    for (int i = 0; i < 10; i++) {
        int idx = tid + i * TPB;
        if (idx >= (AROWS + BROWS) * 8) break;
        if (idx < AROWS * 8) {
            int row = idx >> 3, seg = idx & 7;
            uint32_t d = st + (row * SA + seg * 4) * 4;
            int ab = (m0 + row < N) ? 16 : 0;
            cp16p(d, x + (size_t)(m0 + row) * FIN + kc * BK + seg * 4, ab);
        } else {
            int j = idx - AROWS * 8;
            int row = j >> 3, seg = j & 7;
            uint32_t d = st + OFF_B + (row * SA + seg * 4) * 4;
            cp16(d, g_w1t + (size_t)(n0 + row) * FIN + kc * BK + seg * 4);
        }
    }
}

__global__ void __launch_bounds__(TPB, 2)
k_mma(const float* __restrict__ x, const float* __restrict__ W2,
      const float* __restrict__ b1) {
    extern __shared__ char smem[];
    uint32_t sb = smem_u32(smem);
    const int tid = threadIdx.x, lane = tid & 31, wid = tid >> 5;
    const int m0 = (blockIdx.x >> 2) * AROWS;
    const int n0 = (blockIdx.x & 3) * BROWS;
    const int wm = (wid >> 1) * 32;
    const int wn = (wid & 1) * 64;
    const int gq = lane >> 2, t4 = lane & 3;

    const int lg = lane >> 3, lj = lane & 7;
    const uint32_t aoff = (uint32_t)(((wm + (lg & 1) * 8 + lj) * SA + (lg >> 1) * 4) * 4);
    const uint32_t boff = (uint32_t)(OFF_B +
        ((wn + (lg >> 1) * 8 + lj) * SA + (lg & 1) * 4) * 4);

    float acc[2][8][4];
    #pragma unroll
    for (int t = 0; t < 2; t++)
        #pragma unroll
        for (int nt = 0; nt < 8; nt++)
            #pragma unroll
            for (int q = 0; q < 4; q++) acc[t][nt][q] = 0.0f;

    prefetch(sb, 0, x, m0, n0, 0, tid); CP_COMMIT();
    prefetch(sb, 1, x, m0, n0, 1, tid); CP_COMMIT();

    #pragma unroll 1
    for (int kc = 0; kc < FIN / BK; kc++) {
        if (kc == FIN / BK - 1) CP_WAIT(0); else CP_WAIT(1);
        __syncthreads();
        if (kc + 2 < FIN / BK) {
            prefetch(sb, (kc + 2) % NSTG, x, m0, n0, kc + 2, tid);
            CP_COMMIT();
        }
        uint32_t st = sb + (kc % NSTG) * STGB;
        uint32_t ab = st + aoff;
        uint32_t bb = st + boff;

        #pragma unroll
        for (int s = 0; s < 4; s++) {
            uint32_t af[2][4], bf[4][4];
            LDSM4(af[0], ab + s * 32);
            LDSM4(af[1], ab + s * 32 + 16 * SA * 4);
            #pragma unroll
            for (int p = 0; p < 4; p++)
                LDSM4(bf[p], bb + s * 32 + p * (16 * SA * 4));
            #pragma unroll
            for (int t = 0; t < 2; t++)
                #pragma unroll
                for (int q = 0; q < 4; q++)
                    af[t][q] = to_tf32(__uint_as_float(af[t][q]));
            #pragma unroll
            for (int t = 0; t < 2; t++)
                #pragma unroll
                for (int p = 0; p < 4; p++) {
                    MMA_TF32(acc[t][2 * p],     af[t], bf[p][0], bf[p][1]);
                    MMA_TF32(acc[t][2 * p + 1], af[t], bf[p][2], bf[p][3]);
                }
        }
    }

    // ---- epilogue overlay ----
    __syncthreads();
    float* hs  = (float*)smem;
    float* w2s = (float*)(smem + EPI_W2);
    float* b1s = (float*)(smem + EPI_B1);
    for (int i = tid; i < BROWS * C; i += TPB) w2s[i] = W2[(size_t)n0 * C + i];
    if (tid < BROWS) b1s[tid] = b1[n0 + tid];
    __syncthreads();

    #pragma unroll
    for (int t = 0; t < 2; t++)
        #pragma unroll
        for (int nt = 0; nt < 8; nt++) {
            int r = wm + t * 16 + gq;
            int cc = wn + nt * 8 + 2 * t4;
            float bv0 = b1s[cc], bv1 = b1s[cc + 1];
            float h00 = fmaxf(acc[t][nt][0] + bv0, 0.0f);
            float h01 = fmaxf(acc[t][nt][1] + bv1, 0.0f);
            float h10 = fmaxf(acc[t][nt][2] + bv0, 0.0f);
            float h11 = fmaxf(acc[t][nt][3] + bv1, 0.0f);
            *(float2*)&hs[r * HSS + cc] =
                make_float2(__uint_as_float(to_tf32(h00)), __uint_as_float(to_tf32(h01)));
            *(float2*)&hs[(r + 8) * HSS + cc] =
                make_float2(__uint_as_float(to_tf32(h10)), __uint_as_float(to_tf32(h11)));
        }
    __syncthreads();

    float zacc[5][4];
    #pragma unroll
    for (int nt = 0; nt < 5; nt++)
        #pragma unroll
        for (int q = 0; q < 4; q++) zacc[nt][q] = 0.0f;
    const int rw = wid * 16;

    #pragma unroll
    for (int s = 0; s < 16; s++) {
        const float* hr = hs + (rw + gq) * HSS + s * 8 + t4;
        uint32_t af2[4];
        af2[0] = __float_as_uint(hr[0]);
        af2[1] = __float_as_uint(hr[8 * HSS]);
        af2[2] = __float_as_uint(hr[4]);
        af2[3] = __float_as_uint(hr[8 * HSS + 4]);
        #pragma unroll
        for (int nt = 0; nt < 5; nt++) {
            uint32_t b0 = __float_as_uint(w2s[(s * 8 + t4) * C + nt * 8 + gq]);
            uint32_t b1r = __float_as_uint(w2s[(s * 8 + t4 + 4) * C + nt * 8 + gq]);
            MMA_TF32(zacc[nt], af2, b0, b1r);
        }
    }

    int r1 = m0 + rw + gq, r2 = r1 + 8;
    #pragma unroll
    for (int nt = 0; nt < 5; nt++) {
        int col = nt * 8 + 2 * t4;
        if (r1 < N)
            asm volatile("red.global.add.v2.f32 [%0], {%1,%2};"
                :: "l"(g_Z0 + (size_t)r1 * C + col), "f"(zacc[nt][0]), "f"(zacc[nt][1])
                : "memory");
        if (r2 < N)
            asm volatile("red.global.add.v2.f32 [%0], {%1,%2};"
                :: "l"(g_Z0 + (size_t)r2 * C + col), "f"(zacc[nt][2]), "f"(zacc[nt][3])
                : "memory");
    }
}

// ---------------- APPNP: warp-per-node; SINGLE-LDG fp16 gather --------------
// Gather reads the fp16 shadow as ONE uint2 (LDG.64) — instruction parity
// with the fp32 version (R14's 2x LDG.32 split was the regression cause),
// half the gather sectors. State stays fp32.
__global__ void __launch_bounds__(256)
k_prop(const float* __restrict__ zp, const __half* __restrict__ hp,
       float* __restrict__ out, __half* __restrict__ hout, int writeH) {
    int w = (blockIdx.x * blockDim.x + threadIdx.x) >> 5;
    if (w >= N) return;
    const int lane = threadIdx.x & 31;
    const int g = lane / 10;
    const int q = lane - g * 10;

    float4 acc = make_float4(0.f, 0.f, 0.f, 0.f);
    const int beg = g_base[w];
    const int cnt = g_deg[w] - 1;

    for (int j = (g < 3) ? g : cnt; j < cnt; j += 3) {
        int2 m = g_meta[beg + j];
        float wgt = __int_as_float(m.y);
        uint2 hv = *(const uint2*)(hp + (size_t)m.x * C + q * 4);  // 1x LDG.64
        float2 v01 = __half22float2(*(__half2*)&hv.x);
        float2 v23 = __half22float2(*(__half2*)&hv.y);
        acc.x = fmaf(wgt, v01.x, acc.x);
        acc.y = fmaf(wgt, v01.y, acc.y);
        acc.z = fmaf(wgt, v23.x, acc.z);
        acc.w = fmaf(wgt, v23.y, acc.w);
    }

    float sx1 = __shfl_sync(0xffffffffu, acc.x, lane + 10);
    float sy1 = __shfl_sync(0xffffffffu, acc.y, lane + 10);
    float sz1 = __shfl_sync(0xffffffffu, acc.z, lane + 10);
    float sw1 = __shfl_sync(0xffffffffu, acc.w, lane + 10);
    float sx2 = __shfl_sync(0xffffffffu, acc.x, lane + 20);
    float sy2 = __shfl_sync(0xffffffffu, acc.y, lane + 20);
    float sz2 = __shfl_sync(0xffffffffu, acc.z, lane + 20);
    float sw2 = __shfl_sync(0xffffffffu, acc.w, lane + 20);

    if (g == 0) {
        const size_t off = (size_t)w * C + q * 4;
        float d = g_dinv[w];
        float s = (1.0f - ALPHA) * d * d;
        float4 z0v = *(const float4*)(g_Z0 + off);
        float4 zpv = *(const float4*)(zp + off);
        float4 o;
        o.x = fmaf(s, zpv.x, ALPHA * z0v.x) + acc.x + sx1 + sx2;
        o.y = fmaf(s, zpv.y, ALPHA * z0v.y) + acc.y + sy1 + sy2;
        o.z = fmaf(s, zpv.z, ALPHA * z0v.z) + acc.z + sz1 + sz2;
        o.w = fmaf(s, zpv.w, ALPHA * z0v.w) + acc.w + sw1 + sw2;
        *(float4*)(out + off) = o;
        if (writeH) {
            __half2 h01 = __floats2half2_rn(o.x, o.y);
            __half2 h23 = __floats2half2_rn(o.z, o.w);
            uint2 pk;
            pk.x = *(uint32_t*)&h01;
            pk.y = *(uint32_t*)&h23;
            *(uint2*)(hout + off) = pk;                            // 1x STG.64
        }
    }
}

// ---------------- launch ----------------------------------------------------
extern "C" void kernel_launch(void* const* d_in, const int* in_sizes, int n_in,
                              void* d_out, int out_size) {
    const float* x  = (const float*)d_in[0];
    const float* W1 = (const float*)d_in[1];
    const float* b1 = (const float*)d_in[2];
    const float* W2 = (const float*)d_in[3];
    const float* b2 = (const float*)d_in[4];
    const int*   ei = (const int*)  d_in[5];
    float* out = (float*)d_out;

    float *Z0, *ZA, *ZB;
    __half *HA, *HB;
    cudaGetSymbolAddress((void**)&Z0, g_Z0);
    cudaGetSymbolAddress((void**)&ZA, g_ZA);
    cudaGetSymbolAddress((void**)&ZB, g_ZB);
    cudaGetSymbolAddress((void**)&HA, g_HA);
    cudaGetSymbolAddress((void**)&HB, g_HB);

    // k_mma at our launch index 3 (ncu -s 5 lands there)
    k_cvt_w1  <<<256, 1024>>>(W1);                                  // 0
    k_z0init  <<<(N * 10 + 255) / 256, 256>>>(b2);                  // 1
    k_deg_count<<<(EDG + 255) / 256, 256>>>(ei);                    // 2

    cudaFuncSetAttribute(k_mma, cudaFuncAttributeMaxDynamicSharedMemorySize,
                         GEMM_SMEM);
    k_mma<<<MT * 4, TPB, GEMM_SMEM>>>(x, W2, b1);                   // 3

    k_h0       <<<(N * 10 + 255) / 256, 256>>>();                   // 4
    k_dinv_base<<<(N + 255) / 256, 256>>>();                        // 5
    k_scatter  <<<(EDG + 255) / 256, 256>>>(ei);                    // 6

    const float* zp = Z0;
    const __half* hp = HA;
    for (int it = 1; it <= KITER; it++) {
        float*  tgt  = (it == KITER) ? out : ((it & 1) ? ZA : ZB);
        __half* htgt = (it & 1) ? HB : HA;
        k_prop<<<(N * 32 + 255) / 256, 256>>>(zp, hp, tgt, htgt,
                                              it < KITER ? 1 : 0);
        zp = tgt;
        hp = htgt;
    }
}

// round 16
// speedup vs baseline: 1.0759x; 1.0759x over previous
#include <cuda_runtime.h>
#include <cstdint>

#define N        100000
#define FIN      512
#define HID      512
#define C        40
#define EDG      1600000
#define KITER    10
#define ALPHA    0.1f

// ---------------- scratch (device globals; no allocation allowed) ----------
__device__ float g_Z0[(size_t)N * C];
__device__ float g_ZA[(size_t)N * C];
__device__ float g_ZB[(size_t)N * C];
__device__ float g_dinv[N];
__device__ int   g_deg[N];
__device__ int   g_base[N];
__device__ int   g_slot[EDG];            // within-node ordinal per edge
__device__ int2  g_meta[EDG];
__device__ int   g_total;
__device__ float g_w1t[(size_t)HID * FIN];   // W1^T [n][k], tf32-rounded

// ---------------- PTX helpers ----------------------------------------------
__device__ __forceinline__ uint32_t smem_u32(const void* p) {
    uint32_t a;
    asm("{ .reg .u64 t; cvta.to.shared.u64 t, %1; cvt.u32.u64 %0, t; }"
        : "=r"(a) : "l"(p));
    return a;
}
__device__ __forceinline__ void cp16(uint32_t s, const void* g) {
    asm volatile("cp.async.cg.shared.global [%0], [%1], 16;" :: "r"(s), "l"(g));
}
__device__ __forceinline__ void cp16p(uint32_t s, const void* g, int bytes) {
    asm volatile("cp.async.cg.shared.global [%0], [%1], 16, %2;"
                 :: "r"(s), "l"(g), "r"(bytes));
}
#define CP_COMMIT()  asm volatile("cp.async.commit_group;" ::: "memory")
#define CP_WAIT(n)   asm volatile("cp.async.wait_group %0;" :: "n"(n) : "memory")

__device__ __forceinline__ uint32_t to_tf32(float f) {
    uint32_t u;
    asm("cvt.rna.tf32.f32 %0, %1;" : "=r"(u) : "f"(f));
    return u;
}

#define LDSM4(r, a) \
    asm volatile("ldmatrix.sync.aligned.m8n8.x4.shared.b16 {%0,%1,%2,%3}, [%4];" \
        : "=r"((r)[0]), "=r"((r)[1]), "=r"((r)[2]), "=r"((r)[3]) : "r"(a))

#define MMA_TF32(d, a, b0, b1) \
    asm volatile("mma.sync.aligned.m16n8k8.row.col.f32.tf32.tf32.f32 " \
        "{%0,%1,%2,%3}, {%4,%5,%6,%7}, {%8,%9}, {%0,%1,%2,%3};" \
        : "+f"((d)[0]), "+f"((d)[1]), "+f"((d)[2]), "+f"((d)[3]) \
        : "r"((a)[0]), "r"((a)[1]), "r"((a)[2]), "r"((a)[3]), "r"(b0), "r"(b1))

// ---------------- setup -----------------------------------------------------
// deg count + within-node slot in one pass (atomicAdd's return IS the slot)
__global__ void k_deg_count(const int* __restrict__ ei) {
    int e = blockIdx.x * blockDim.x + threadIdx.x;
    if (e < EDG) {
        int old = atomicAdd(&g_deg[ei[e]], 1);   // deg starts at 1 (self-loop)
        g_slot[e] = old - 1;                     // 0-based real-edge ordinal
    }
}
__global__ void k_dinv_base() {
    int i = blockIdx.x * blockDim.x + threadIdx.x;
    if (i < N) {
        int d = g_deg[i];
        g_dinv[i] = rsqrtf((float)d);
        g_base[i] = atomicAdd(&g_total, d - 1);
    }
}
// no cursor atomic: pos = base[row] + slot[e]
__global__ void k_scatter(const int* __restrict__ ei) {
    int e = blockIdx.x * blockDim.x + threadIdx.x;
    if (e < EDG) {
        int r = ei[e];
        int s = ei[EDG + e];
        float w = (1.0f - ALPHA) * g_dinv[r] * g_dinv[s];
        int pos = g_base[r] + g_slot[e];
        g_meta[pos] = make_int2(s, __float_as_int(w));
    }
}

// W1 [k][n] -> g_w1t [n][k], tf32-rounded
__global__ void k_cvt_w1(const float* __restrict__ W1) {
    __shared__ float t[32][33];
    int bx = blockIdx.x & 15, by = blockIdx.x >> 4;
    int tx = threadIdx.x & 31, ty = threadIdx.x >> 5;
    t[ty][tx] = W1[(size_t)(by * 32 + ty) * HID + bx * 32 + tx];
    __syncthreads();
    int n = bx * 32 + ty, k = by * 32 + tx;
    g_w1t[(size_t)n * FIN + k] = __uint_as_float(to_tf32(t[tx][ty]));
}

// z0 = b2 broadcast; folds deg/total reset
__global__ void k_z0init(const float* __restrict__ b2) {
    unsigned t = blockIdx.x * blockDim.x + threadIdx.x;
    if (t >= (unsigned)N * 10u) return;
    unsigned c = t % 10u;
    ((float4*)g_Z0)[t] = ((const float4*)b2)[c];
    if (t < N) g_deg[t] = 1;
    if (t == 0) g_total = 0;
}

// ---------------- TF32 GEMM1 + tensor-core GEMM2 epilogue (FROZEN) ----------
#define BK      32
#define SA      36
#define AROWS   96
#define BROWS   128
#define OFF_B   (AROWS * SA * 4)
#define STGB    ((AROWS + BROWS) * SA * 4)
#define NSTG    3
#define GEMM_SMEM (NSTG * STGB)           // 96768
#define TPB     192
#define MT      ((N + AROWS - 1) / AROWS) // 1042
#define HSS     132
#define EPI_W2  (AROWS * HSS * 4)
#define EPI_B1  (EPI_W2 + BROWS * C * 4)

__device__ __forceinline__ void prefetch(uint32_t sb, int stage,
                                         const float* __restrict__ x,
                                         int m0, int n0, int kc, int tid) {
    uint32_t st = sb + stage * STGB;
    #pragma unroll
    for (int i = 0; i < 10; i++) {
        int idx = tid + i * TPB;
        if (idx >= (AROWS + BROWS) * 8) break;
        if (idx < AROWS * 8) {
            int row = idx >> 3, seg = idx & 7;
            uint32_t d = st + (row * SA + seg * 4) * 4;
            int ab = (m0 + row < N) ? 16 : 0;
            cp16p(d, x + (size_t)(m0 + row) * FIN + kc * BK + seg * 4, ab);
        } else {
            int j = idx - AROWS * 8;
            int row = j >> 3, seg = j & 7;
            uint32_t d = st + OFF_B + (row * SA + seg * 4) * 4;
            cp16(d, g_w1t + (size_t)(n0 + row) * FIN + kc * BK + seg * 4);
        }
    }
}

__global__ void __launch_bounds__(TPB, 2)
k_mma(const float* __restrict__ x, const float* __restrict__ W2,
      const float* __restrict__ b1) {
    extern __shared__ char smem[];
    uint32_t sb = smem_u32(smem);
    const int tid = threadIdx.x, lane = tid & 31, wid = tid >> 5;
    const int m0 = (blockIdx.x >> 2) * AROWS;
    const int n0 = (blockIdx.x & 3) * BROWS;
    const int wm = (wid >> 1) * 32;
    const int wn = (wid & 1) * 64;
    const int gq = lane >> 2, t4 = lane & 3;

    const int lg = lane >> 3, lj = lane & 7;
    const uint32_t aoff = (uint32_t)(((wm + (lg & 1) * 8 + lj) * SA + (lg >> 1) * 4) * 4);
    const uint32_t boff = (uint32_t)(OFF_B +
        ((wn + (lg >> 1) * 8 + lj) * SA + (lg & 1) * 4) * 4);

    float acc[2][8][4];
    #pragma unroll
    for (int t = 0; t < 2; t++)
        #pragma unroll
        for (int nt = 0; nt < 8; nt++)
            #pragma unroll
            for (int q = 0; q < 4; q++) acc[t][nt][q] = 0.0f;

    prefetch(sb, 0, x, m0, n0, 0, tid); CP_COMMIT();
    prefetch(sb, 1, x, m0, n0, 1, tid); CP_COMMIT();

    #pragma unroll 1
    for (int kc = 0; kc < FIN / BK; kc++) {
        if (kc == FIN / BK - 1) CP_WAIT(0); else CP_WAIT(1);
        __syncthreads();
        if (kc + 2 < FIN / BK) {
            prefetch(sb, (kc + 2) % NSTG, x, m0, n0, kc + 2, tid);
            CP_COMMIT();
        }
        uint32_t st = sb + (kc % NSTG) * STGB;
        uint32_t ab = st + aoff;
        uint32_t bb = st + boff;

        #pragma unroll
        for (int s = 0; s < 4; s++) {
            uint32_t af[2][4], bf[4][4];
            LDSM4(af[0], ab + s * 32);
            LDSM4(af[1], ab + s * 32 + 16 * SA * 4);
            #pragma unroll
            for (int p = 0; p < 4; p++)
                LDSM4(bf[p], bb + s * 32 + p * (16 * SA * 4));
            #pragma unroll
            for (int t = 0; t < 2; t++)
                #pragma unroll
                for (int q = 0; q < 4; q++)
                    af[t][q] = to_tf32(__uint_as_float(af[t][q]));
            #pragma unroll
            for (int t = 0; t < 2; t++)
                #pragma unroll
                for (int p = 0; p < 4; p++) {
                    MMA_TF32(acc[t][2 * p],     af[t], bf[p][0], bf[p][1]);
                    MMA_TF32(acc[t][2 * p + 1], af[t], bf[p][2], bf[p][3]);
                }
        }
    }

    // ---- epilogue overlay ----
    __syncthreads();
    float* hs  = (float*)smem;
    float* w2s = (float*)(smem + EPI_W2);
    float* b1s = (float*)(smem + EPI_B1);
    for (int i = tid; i < BROWS * C; i += TPB) w2s[i] = W2[(size_t)n0 * C + i];
    if (tid < BROWS) b1s[tid] = b1[n0 + tid];
    __syncthreads();

    #pragma unroll
    for (int t = 0; t < 2; t++)
        #pragma unroll
        for (int nt = 0; nt < 8; nt++) {
            int r = wm + t * 16 + gq;
            int cc = wn + nt * 8 + 2 * t4;
            float bv0 = b1s[cc], bv1 = b1s[cc + 1];
            float h00 = fmaxf(acc[t][nt][0] + bv0, 0.0f);
            float h01 = fmaxf(acc[t][nt][1] + bv1, 0.0f);
            float h10 = fmaxf(acc[t][nt][2] + bv0, 0.0f);
            float h11 = fmaxf(acc[t][nt][3] + bv1, 0.0f);
            *(float2*)&hs[r * HSS + cc] =
                make_float2(__uint_as_float(to_tf32(h00)), __uint_as_float(to_tf32(h01)));
            *(float2*)&hs[(r + 8) * HSS + cc] =
                make_float2(__uint_as_float(to_tf32(h10)), __uint_as_float(to_tf32(h11)));
        }
    __syncthreads();

    float zacc[5][4];
    #pragma unroll
    for (int nt = 0; nt < 5; nt++)
        #pragma unroll
        for (int q = 0; q < 4; q++) zacc[nt][q] = 0.0f;
    const int rw = wid * 16;

    #pragma unroll
    for (int s = 0; s < 16; s++) {
        const float* hr = hs + (rw + gq) * HSS + s * 8 + t4;
        uint32_t af2[4];
        af2[0] = __float_as_uint(hr[0]);
        af2[1] = __float_as_uint(hr[8 * HSS]);
        af2[2] = __float_as_uint(hr[4]);
        af2[3] = __float_as_uint(hr[8 * HSS + 4]);
        #pragma unroll
        for (int nt = 0; nt < 5; nt++) {
            uint32_t b0 = __float_as_uint(w2s[(s * 8 + t4) * C + nt * 8 + gq]);
            uint32_t b1r = __float_as_uint(w2s[(s * 8 + t4 + 4) * C + nt * 8 + gq]);
            MMA_TF32(zacc[nt], af2, b0, b1r);
        }
    }

    int r1 = m0 + rw + gq, r2 = r1 + 8;
    #pragma unroll
    for (int nt = 0; nt < 5; nt++) {
        int col = nt * 8 + 2 * t4;
        if (r1 < N)
            asm volatile("red.global.add.v2.f32 [%0], {%1,%2};"
                :: "l"(g_Z0 + (size_t)r1 * C + col), "f"(zacc[nt][0]), "f"(zacc[nt][1])
                : "memory");
        if (r2 < N)
            asm volatile("red.global.add.v2.f32 [%0], {%1,%2};"
                :: "l"(g_Z0 + (size_t)r2 * C + col), "f"(zacc[nt][2]), "f"(zacc[nt][3])
                : "memory");
    }
}

// ---------------- APPNP: warp-per-node, 3 edges/trip (R13 version) ----------
__global__ void __launch_bounds__(256)
k_prop(const float* __restrict__ zp, float* __restrict__ out) {
    int w = (blockIdx.x * blockDim.x + threadIdx.x) >> 5;
    if (w >= N) return;
    const int lane = threadIdx.x & 31;
    const int g = lane / 10;
    const int q = lane - g * 10;

    float4 acc = make_float4(0.f, 0.f, 0.f, 0.f);
    const int beg = g_base[w];
    const int cnt = g_deg[w] - 1;

    for (int j = (g < 3) ? g : cnt; j < cnt; j += 3) {
        int2 m = g_meta[beg + j];
        float wgt = __int_as_float(m.y);
        float4 v = *(const float4*)(zp + (size_t)m.x * C + q * 4);
        acc.x = fmaf(wgt, v.x, acc.x);
        acc.y = fmaf(wgt, v.y, acc.y);
        acc.z = fmaf(wgt, v.z, acc.z);
        acc.w = fmaf(wgt, v.w, acc.w);
    }

    float sx1 = __shfl_sync(0xffffffffu, acc.x, lane + 10);
    float sy1 = __shfl_sync(0xffffffffu, acc.y, lane + 10);
    float sz1 = __shfl_sync(0xffffffffu, acc.z, lane + 10);
    float sw1 = __shfl_sync(0xffffffffu, acc.w, lane + 10);
    float sx2 = __shfl_sync(0xffffffffu, acc.x, lane + 20);
    float sy2 = __shfl_sync(0xffffffffu, acc.y, lane + 20);
    float sz2 = __shfl_sync(0xffffffffu, acc.z, lane + 20);
    float sw2 = __shfl_sync(0xffffffffu, acc.w, lane + 20);

    if (g == 0) {
        const size_t off = (size_t)w * C + q * 4;
        float d = g_dinv[w];
        float s = (1.0f - ALPHA) * d * d;
        float4 z0v = *(const float4*)(g_Z0 + off);
        float4 zpv = *(const float4*)(zp + off);
        float4 o;
        o.x = fmaf(s, zpv.x, ALPHA * z0v.x) + acc.x + sx1 + sx2;
        o.y = fmaf(s, zpv.y, ALPHA * z0v.y) + acc.y + sy1 + sy2;
        o.z = fmaf(s, zpv.z, ALPHA * z0v.z) + acc.z + sz1 + sz2;
        o.w = fmaf(s, zpv.w, ALPHA * z0v.w) + acc.w + sw1 + sw2;
        *(float4*)(out + off) = o;
    }
}

// ---------------- launch ----------------------------------------------------
extern "C" void kernel_launch(void* const* d_in, const int* in_sizes, int n_in,
                              void* d_out, int out_size) {
    const float* x  = (const float*)d_in[0];
    const float* W1 = (const float*)d_in[1];
    const float* b1 = (const float*)d_in[2];
    const float* W2 = (const float*)d_in[3];
    const float* b2 = (const float*)d_in[4];
    const int*   ei = (const int*)  d_in[5];
    float* out = (float*)d_out;

    float *Z0, *ZA, *ZB;
    cudaGetSymbolAddress((void**)&Z0, g_Z0);
    cudaGetSymbolAddress((void**)&ZA, g_ZA);
    cudaGetSymbolAddress((void**)&ZB, g_ZB);

    // k_mma at our launch index 3 (ncu -s 5 lands there)
    k_cvt_w1  <<<256, 1024>>>(W1);                                  // 0
    k_z0init  <<<(N * 10 + 255) / 256, 256>>>(b2);                  // 1
    k_deg_count<<<(EDG + 255) / 256, 256>>>(ei);                    // 2

    cudaFuncSetAttribute(k_mma, cudaFuncAttributeMaxDynamicSharedMemorySize,
                         GEMM_SMEM);
    k_mma<<<MT * 4, TPB, GEMM_SMEM>>>(x, W2, b1);                   // 3

    k_dinv_base<<<(N + 255) / 256, 256>>>();                        // 4
    k_scatter  <<<(EDG + 255) / 256, 256>>>(ei);                    // 5

    const float* zp = Z0;
    for (int it = 1; it <= KITER; it++) {
        float* tgt = (it == KITER) ? out : ((it & 1) ? ZA : ZB);
        k_prop<<<(N * 32 + 255) / 256, 256>>>(zp, tgt);
        zp = tgt;
    }
}

// round 17
// speedup vs baseline: 1.1018x; 1.0241x over previous
#include <cuda_runtime.h>
#include <cstdint>

#define N        100000
#define FIN      512
#define HID      512
#define C        40
#define EDG      1600000
#define KITER    10
#define ALPHA    0.1f

// ---------------- scratch (device globals; no allocation allowed) ----------
__device__ float g_Z0[(size_t)N * C];
__device__ float g_ZA[(size_t)N * C];
__device__ float g_ZB[(size_t)N * C];
__device__ float g_dinv[N];
__device__ int   g_deg[N];
__device__ int   g_base[N];
__device__ int   g_cursor[N];
__device__ int2  g_meta[EDG];
__device__ int   g_total;
__device__ float g_w1t[(size_t)HID * FIN];   // W1^T [n][k], tf32-rounded

// ---------------- PTX helpers ----------------------------------------------
__device__ __forceinline__ uint32_t smem_u32(const void* p) {
    uint32_t a;
    asm("{ .reg .u64 t; cvta.to.shared.u64 t, %1; cvt.u32.u64 %0, t; }"
        : "=r"(a) : "l"(p));
    return a;
}
__device__ __forceinline__ void cp16(uint32_t s, const void* g) {
    asm volatile("cp.async.cg.shared.global [%0], [%1], 16;" :: "r"(s), "l"(g));
}
__device__ __forceinline__ void cp16p(uint32_t s, const void* g, int bytes) {
    asm volatile("cp.async.cg.shared.global [%0], [%1], 16, %2;"
                 :: "r"(s), "l"(g), "r"(bytes));
}
#define CP_COMMIT()  asm volatile("cp.async.commit_group;" ::: "memory")
#define CP_WAIT(n)   asm volatile("cp.async.wait_group %0;" :: "n"(n) : "memory")

__device__ __forceinline__ uint32_t to_tf32(float f) {
    uint32_t u;
    asm("cvt.rna.tf32.f32 %0, %1;" : "=r"(u) : "f"(f));
    return u;
}

#define LDSM4(r, a) \
    asm volatile("ldmatrix.sync.aligned.m8n8.x4.shared.b16 {%0,%1,%2,%3}, [%4];" \
        : "=r"((r)[0]), "=r"((r)[1]), "=r"((r)[2]), "=r"((r)[3]) : "r"(a))

#define MMA_TF32(d, a, b0, b1) \
    asm volatile("mma.sync.aligned.m16n8k8.row.col.f32.tf32.tf32.f32 " \
        "{%0,%1,%2,%3}, {%4,%5,%6,%7}, {%8,%9}, {%0,%1,%2,%3};" \
        : "+f"((d)[0]), "+f"((d)[1]), "+f"((d)[2]), "+f"((d)[3]) \
        : "r"((a)[0]), "r"((a)[1]), "r"((a)[2]), "r"((a)[3]), "r"(b0), "r"(b1))

// ---------------- setup -----------------------------------------------------
// NOTE: atomicAdd return value intentionally unused -> compiles to REDG
// (fire-and-forget). R16 showed that consuming it (ATOMG w/ return, 318 cyc)
// costs more than the cursor atomic it saved.
__global__ void k_deg_count(const int* __restrict__ ei) {
    int e = blockIdx.x * blockDim.x + threadIdx.x;
    if (e < EDG) atomicAdd(&g_deg[ei[e]], 1);
}
__global__ void k_dinv_base() {
    int i = blockIdx.x * blockDim.x + threadIdx.x;
    if (i < N) {
        int d = g_deg[i];
        g_dinv[i] = rsqrtf((float)d);
        int b = atomicAdd(&g_total, d - 1);
        g_base[i] = b;
        g_cursor[i] = b;
    }
}
__global__ void k_scatter(const int* __restrict__ ei) {
    int e = blockIdx.x * blockDim.x + threadIdx.x;
    if (e < EDG) {
        int r = ei[e];
        int s = ei[EDG + e];
        float w = (1.0f - ALPHA) * g_dinv[r] * g_dinv[s];
        int pos = atomicAdd(&g_cursor[r], 1);
        g_meta[pos] = make_int2(s, __float_as_int(w));
    }
}

// W1 [k][n] -> g_w1t [n][k], tf32-rounded
__global__ void k_cvt_w1(const float* __restrict__ W1) {
    __shared__ float t[32][33];
    int bx = blockIdx.x & 15, by = blockIdx.x >> 4;
    int tx = threadIdx.x & 31, ty = threadIdx.x >> 5;
    t[ty][tx] = W1[(size_t)(by * 32 + ty) * HID + bx * 32 + tx];
    __syncthreads();
    int n = bx * 32 + ty, k = by * 32 + tx;
    g_w1t[(size_t)n * FIN + k] = __uint_as_float(to_tf32(t[tx][ty]));
}

// z0 = b2 broadcast; folds deg/total reset
__global__ void k_z0init(const float* __restrict__ b2) {
    unsigned t = blockIdx.x * blockDim.x + threadIdx.x;
    if (t >= (unsigned)N * 10u) return;
    unsigned c = t % 10u;
    ((float4*)g_Z0)[t] = ((const float4*)b2)[c];
    if (t < N) g_deg[t] = 1;
    if (t == 0) g_total = 0;
}

// ---------------- TF32 GEMM1 + tensor-core GEMM2 epilogue (FROZEN) ----------
// CTA 96x128, 6 warps (32x64 warp tiles), 192 threads, 2 CTAs/SM, ldmatrix
// fragments, 4168-CTA launch. Pinned at the ~52% legacy-HMMA tf32 ceiling
// (5 configs tested R5-R9); wave quantization beats persistent-K (R12).
#define BK      32
#define SA      36
#define AROWS   96
#define BROWS   128
#define OFF_B   (AROWS * SA * 4)
#define STGB    ((AROWS + BROWS) * SA * 4)
#define NSTG    3
#define GEMM_SMEM (NSTG * STGB)           // 96768
#define TPB     192
#define MT      ((N + AROWS - 1) / AROWS) // 1042
#define HSS     132
#define EPI_W2  (AROWS * HSS * 4)
#define EPI_B1  (EPI_W2 + BROWS * C * 4)

__device__ __forceinline__ void prefetch(uint32_t sb, int stage,
                                         const float* __restrict__ x,
                                         int m0, int n0, int kc, int tid) {
    uint32_t st = sb + stage * STGB;
    #pragma unroll
    for (int i = 0; i < 10; i++) {
        int idx = tid + i * TPB;
        if (idx >= (AROWS + BROWS) * 8) break;
        if (idx < AROWS * 8) {
            int row = idx >> 3, seg = idx & 7;
            uint32_t d = st + (row * SA + seg * 4) * 4;
            int ab = (m0 + row < N) ? 16 : 0;
            cp16p(d, x + (size_t)(m0 + row) * FIN + kc * BK + seg * 4, ab);
        } else {
            int j = idx - AROWS * 8;
            int row = j >> 3, seg = j & 7;
            uint32_t d = st + OFF_B + (row * SA + seg * 4) * 4;
            cp16(d, g_w1t + (size_t)(n0 + row) * FIN + kc * BK + seg * 4);
        }
    }
}

__global__ void __launch_bounds__(TPB, 2)
k_mma(const float* __restrict__ x, const float* __restrict__ W2,
      const float* __restrict__ b1) {
    extern __shared__ char smem[];
    uint32_t sb = smem_u32(smem);
    const int tid = threadIdx.x, lane = tid & 31, wid = tid >> 5;
    const int m0 = (blockIdx.x >> 2) * AROWS;
    const int n0 = (blockIdx.x & 3) * BROWS;
    const int wm = (wid >> 1) * 32;
    const int wn = (wid & 1) * 64;
    const int gq = lane >> 2, t4 = lane & 3;

    const int lg = lane >> 3, lj = lane & 7;
    const uint32_t aoff = (uint32_t)(((wm + (lg & 1) * 8 + lj) * SA + (lg >> 1) * 4) * 4);
    const uint32_t boff = (uint32_t)(OFF_B +
        ((wn + (lg >> 1) * 8 + lj) * SA + (lg & 1) * 4) * 4);

    float acc[2][8][4];
    #pragma unroll
    for (int t = 0; t < 2; t++)
        #pragma unroll
        for (int nt = 0; nt < 8; nt++)
            #pragma unroll
            for (int q = 0; q < 4; q++) acc[t][nt][q] = 0.0f;

    prefetch(sb, 0, x, m0, n0, 0, tid); CP_COMMIT();
    prefetch(sb, 1, x, m0, n0, 1, tid); CP_COMMIT();

    #pragma unroll 1
    for (int kc = 0; kc < FIN / BK; kc++) {
        if (kc == FIN / BK - 1) CP_WAIT(0); else CP_WAIT(1);
        __syncthreads();
        if (kc + 2 < FIN / BK) {
            prefetch(sb, (kc + 2) % NSTG, x, m0, n0, kc + 2, tid);
            CP_COMMIT();
        }
        uint32_t st = sb + (kc % NSTG) * STGB;
        uint32_t ab = st + aoff;
        uint32_t bb = st + boff;

        #pragma unroll
        for (int s = 0; s < 4; s++) {
            uint32_t af[2][4], bf[4][4];
            LDSM4(af[0], ab + s * 32);
            LDSM4(af[1], ab + s * 32 + 16 * SA * 4);
            #pragma unroll
            for (int p = 0; p < 4; p++)
                LDSM4(bf[p], bb + s * 32 + p * (16 * SA * 4));
            #pragma unroll
            for (int t = 0; t < 2; t++)
                #pragma unroll
                for (int q = 0; q < 4; q++)
                    af[t][q] = to_tf32(__uint_as_float(af[t][q]));
            #pragma unroll
            for (int t = 0; t < 2; t++)
                #pragma unroll
                for (int p = 0; p < 4; p++) {
                    MMA_TF32(acc[t][2 * p],     af[t], bf[p][0], bf[p][1]);
                    MMA_TF32(acc[t][2 * p + 1], af[t], bf[p][2], bf[p][3]);
                }
        }
    }

    // ---- epilogue overlay ----
    __syncthreads();
    float* hs  = (float*)smem;
    float* w2s = (float*)(smem + EPI_W2);
    float* b1s = (float*)(smem + EPI_B1);
    for (int i = tid; i < BROWS * C; i += TPB) w2s[i] = W2[(size_t)n0 * C + i];
    if (tid < BROWS) b1s[tid] = b1[n0 + tid];
    __syncthreads();

    #pragma unroll
    for (int t = 0; t < 2; t++)
        #pragma unroll
        for (int nt = 0; nt < 8; nt++) {
            int r = wm + t * 16 + gq;
            int cc = wn + nt * 8 + 2 * t4;
            float bv0 = b1s[cc], bv1 = b1s[cc + 1];
            float h00 = fmaxf(acc[t][nt][0] + bv0, 0.0f);
            float h01 = fmaxf(acc[t][nt][1] + bv1, 0.0f);
            float h10 = fmaxf(acc[t][nt][2] + bv0, 0.0f);
            float h11 = fmaxf(acc[t][nt][3] + bv1, 0.0f);
            *(float2*)&hs[r * HSS + cc] =
                make_float2(__uint_as_float(to_tf32(h00)), __uint_as_float(to_tf32(h01)));
            *(float2*)&hs[(r + 8) * HSS + cc] =
                make_float2(__uint_as_float(to_tf32(h10)), __uint_as_float(to_tf32(h11)));
        }
    __syncthreads();

    float zacc[5][4];
    #pragma unroll
    for (int nt = 0; nt < 5; nt++)
        #pragma unroll
        for (int q = 0; q < 4; q++) zacc[nt][q] = 0.0f;
    const int rw = wid * 16;

    #pragma unroll
    for (int s = 0; s < 16; s++) {
        const float* hr = hs + (rw + gq) * HSS + s * 8 + t4;
        uint32_t af2[4];
        af2[0] = __float_as_uint(hr[0]);
        af2[1] = __float_as_uint(hr[8 * HSS]);
        af2[2] = __float_as_uint(hr[4]);
        af2[3] = __float_as_uint(hr[8 * HSS + 4]);
        #pragma unroll
        for (int nt = 0; nt < 5; nt++) {
            uint32_t b0 = __float_as_uint(w2s[(s * 8 + t4) * C + nt * 8 + gq]);
            uint32_t b1r = __float_as_uint(w2s[(s * 8 + t4 + 4) * C + nt * 8 + gq]);
            MMA_TF32(zacc[nt], af2, b0, b1r);
        }
    }

    int r1 = m0 + rw + gq, r2 = r1 + 8;
    #pragma unroll
    for (int nt = 0; nt < 5; nt++) {
        int col = nt * 8 + 2 * t4;
        if (r1 < N)
            asm volatile("red.global.add.v2.f32 [%0], {%1,%2};"
                :: "l"(g_Z0 + (size_t)r1 * C + col), "f"(zacc[nt][0]), "f"(zacc[nt][1])
                : "memory");
        if (r2 < N)
            asm volatile("red.global.add.v2.f32 [%0], {%1,%2};"
                :: "l"(g_Z0 + (size_t)r2 * C + col), "f"(zacc[nt][2]), "f"(zacc[nt][3])
                : "memory");
    }
}

// ---------------- APPNP: warp-per-node, 3 edges/trip ------------------------
// fp32 gather at the LTS cap (~12 TB/s); fp16 shadow falsified twice (R14/15).
__global__ void __launch_bounds__(256)
k_prop(const float* __restrict__ zp, float* __restrict__ out) {
    int w = (blockIdx.x * blockDim.x + threadIdx.x) >> 5;
    if (w >= N) return;
    const int lane = threadIdx.x & 31;
    const int g = lane / 10;
    const int q = lane - g * 10;

    float4 acc = make_float4(0.f, 0.f, 0.f, 0.f);
    const int beg = g_base[w];
    const int cnt = g_deg[w] - 1;

    for (int j = (g < 3) ? g : cnt; j < cnt; j += 3) {
        int2 m = g_meta[beg + j];
        float wgt = __int_as_float(m.y);
        float4 v = *(const float4*)(zp + (size_t)m.x * C + q * 4);
        acc.x = fmaf(wgt, v.x, acc.x);
        acc.y = fmaf(wgt, v.y, acc.y);
        acc.z = fmaf(wgt, v.z, acc.z);
        acc.w = fmaf(wgt, v.w, acc.w);
    }

    float sx1 = __shfl_sync(0xffffffffu, acc.x, lane + 10);
    float sy1 = __shfl_sync(0xffffffffu, acc.y, lane + 10);
    float sz1 = __shfl_sync(0xffffffffu, acc.z, lane + 10);
    float sw1 = __shfl_sync(0xffffffffu, acc.w, lane + 10);
    float sx2 = __shfl_sync(0xffffffffu, acc.x, lane + 20);
    float sy2 = __shfl_sync(0xffffffffu, acc.y, lane + 20);
    float sz2 = __shfl_sync(0xffffffffu, acc.z, lane + 20);
    float sw2 = __shfl_sync(0xffffffffu, acc.w, lane + 20);

    if (g == 0) {
        const size_t off = (size_t)w * C + q * 4;
        float d = g_dinv[w];
        float s = (1.0f - ALPHA) * d * d;
        float4 z0v = *(const float4*)(g_Z0 + off);
        float4 zpv = *(const float4*)(zp + off);
        float4 o;
        o.x = fmaf(s, zpv.x, ALPHA * z0v.x) + acc.x + sx1 + sx2;
        o.y = fmaf(s, zpv.y, ALPHA * z0v.y) + acc.y + sy1 + sy2;
        o.z = fmaf(s, zpv.z, ALPHA * z0v.z) + acc.z + sz1 + sz2;
        o.w = fmaf(s, zpv.w, ALPHA * z0v.w) + acc.w + sw1 + sw2;
        *(float4*)(out + off) = o;
    }
}

// ---------------- launch ----------------------------------------------------
extern "C" void kernel_launch(void* const* d_in, const int* in_sizes, int n_in,
                              void* d_out, int out_size) {
    const float* x  = (const float*)d_in[0];
    const float* W1 = (const float*)d_in[1];
    const float* b1 = (const float*)d_in[2];
    const float* W2 = (const float*)d_in[3];
    const float* b2 = (const float*)d_in[4];
    const int*   ei = (const int*)  d_in[5];
    float* out = (float*)d_out;

    float *Z0, *ZA, *ZB;
    cudaGetSymbolAddress((void**)&Z0, g_Z0);
    cudaGetSymbolAddress((void**)&ZA, g_ZA);
    cudaGetSymbolAddress((void**)&ZB, g_ZB);

    // k_mma at our launch index 3 (ncu -s 5 lands there)
    k_cvt_w1  <<<256, 1024>>>(W1);                                  // 0
    k_z0init  <<<(N * 10 + 255) / 256, 256>>>(b2);                  // 1
    k_deg_count<<<(EDG + 255) / 256, 256>>>(ei);                    // 2

    cudaFuncSetAttribute(k_mma, cudaFuncAttributeMaxDynamicSharedMemorySize,
                         GEMM_SMEM);
    k_mma<<<MT * 4, TPB, GEMM_SMEM>>>(x, W2, b1);                   // 3

    k_dinv_base<<<(N + 255) / 256, 256>>>();                        // 4
    k_scatter  <<<(EDG + 255) / 256, 256>>>(ei);                    // 5

    const float* zp = Z0;
    for (int it = 1; it <= KITER; it++) {
        float* tgt = (it == KITER) ? out : ((it & 1) ? ZA : ZB);
        k_prop<<<(N * 32 + 255) / 256, 256>>>(zp, tgt);
        zp = tgt;
    }
}